// round 1
// baseline (speedup 1.0000x reference)
#include <cuda_runtime.h>
#include <cstdint>

#define M 8192
#define NW 128          // 64-bit words per row (M/64)
#define NMS_T 0.3f

// ---------------- device scratch (no runtime allocation allowed) ------------
__device__ float              g_d[M * 5];       // transformed detections (orig order)
__device__ float              g_score[M];       // score (orig order)
__device__ unsigned int       g_key[M];         // sort key (orig order)
__device__ float              g_ds[M * 5];      // sorted detections
__device__ float              g_ss[M];          // sorted scores
__device__ float4             g_boxes[M];       // x1,y1,x2,y2 (sorted order)
__device__ float              g_area[M];
__device__ int                g_V;              // number of valid (score>0) entries
__device__ unsigned long long g_mask[M * NW];   // suppression bitmask (8 MB)
__device__ unsigned long long g_keepw[NW];      // keep bits

// ---------------- kernel 1: transform + score + sort key --------------------
__global__ void prep_kernel(const float* __restrict__ det,
                            const float* __restrict__ off,
                            const float* __restrict__ scl,
                            const float* __restrict__ bnd) {
    int i = blockIdx.x * blockDim.x + threadIdx.x;
    if (i >= M) return;
    int w = i >> 10;
    const float* dp = det + i * 5;
    float d0 = off[w * 5 + 0] + dp[0] * scl[w * 5 + 0];
    float d1 = off[w * 5 + 1] + dp[1] * scl[w * 5 + 1];
    float d2 = off[w * 5 + 2] + dp[2] * scl[w * 5 + 2];
    float d3 = off[w * 5 + 3] + dp[3] * scl[w * 5 + 3];
    float d4 = off[w * 5 + 4] + dp[4] * scl[w * 5 + 4];
    float cx = dp[1], cy = dp[2];
    bool valid = (cx < bnd[w * 4 + 1]) && (cx > bnd[w * 4 + 0]) &&
                 (cy < bnd[w * 4 + 3]) && (cy > bnd[w * 4 + 2]);
    float score = valid ? d0 : -1.0f;

    g_d[i * 5 + 0] = d0;
    g_d[i * 5 + 1] = d1;
    g_d[i * 5 + 2] = d2;
    g_d[i * 5 + 3] = d3;
    g_d[i * 5 + 4] = d4;
    g_score[i] = score;

    // order-preserving float->uint (ascending), then invert for descending
    unsigned u = __float_as_uint(score);
    u = (u & 0x80000000u) ? ~u : (u | 0x80000000u);
    g_key[i] = ~u;   // ascending key == descending score
}

// ---------------- kernel 2: single-block bitonic sort + gather --------------
// shared: 8192 u32 keys (32KB) + 8192 u16 indices (16KB) = 48KB dynamic
extern "C" __global__ void __launch_bounds__(1024)
sort_kernel() {
    extern __shared__ char smem[];
    unsigned int*   sk = (unsigned int*)smem;
    unsigned short* si = (unsigned short*)(smem + M * sizeof(unsigned int));
    int tid = threadIdx.x;

    for (int t = tid; t < M; t += 1024) {
        sk[t] = g_key[t];
        si[t] = (unsigned short)t;
    }
    __syncthreads();

    for (int k = 2; k <= M; k <<= 1) {
        for (int s = k >> 1; s > 0; s >>= 1) {
            for (int t = tid; t < M; t += 1024) {
                int p = t ^ s;
                if (p > t) {
                    bool up = ((t & k) == 0);
                    unsigned int a = sk[t], b = sk[p];
                    unsigned short ia = si[t], ib = si[p];
                    bool gt = (a > b) || (a == b && ia > ib);
                    if (gt == up) {
                        sk[t] = b; sk[p] = a;
                        si[t] = ib; si[p] = ia;
                    }
                }
            }
            __syncthreads();
        }
    }

    // gather sorted rows, build boxes/areas, find valid count V
    for (int j = tid; j < M; j += 1024) {
        int idx = si[j];
        float dd[5];
#pragma unroll
        for (int c = 0; c < 5; c++) {
            dd[c] = g_d[idx * 5 + c];
            g_ds[j * 5 + c] = dd[c];
        }
        float s = g_score[idx];
        g_ss[j] = s;
        float x1 = dd[1] - 0.5f * dd[3];
        float y1 = dd[2] - 0.5f * dd[4];
        float x2 = dd[1] + 0.5f * dd[3];
        float y2 = dd[2] + 0.5f * dd[4];
        g_boxes[j] = make_float4(x1, y1, x2, y2);
        g_area[j] = fmaxf(x2 - x1, 0.0f) * fmaxf(y2 - y1, 0.0f);

        if (s > 0.0f) {
            if (j == M - 1) g_V = M;
            else if (g_score[si[j + 1]] <= 0.0f) g_V = j + 1;
        } else if (j == 0) {
            g_V = 0;
        }
    }
}

// ---------------- kernel 3: IoU suppression bitmask -------------------------
// block (bx = col chunk, by = row chunk), 64 threads, each = one row
__global__ void mask_kernel() {
    int bx = blockIdx.x, by = blockIdx.y;
    if (bx < by) return;                       // only i > j bits needed
    if (g_ss[by * 64] <= 0.0f) return;         // whole row chunk invalid
    if (g_ss[bx * 64] <= 0.0f) return;         // whole col chunk invalid

    __shared__ float4 cbox[64];
    __shared__ float  carea[64];
    int t = threadIdx.x;
    int ci = bx * 64 + t;
    cbox[t] = g_boxes[ci];
    carea[t] = g_area[ci];
    __syncthreads();

    int j = by * 64 + t;
    if (g_ss[j] <= 0.0f) return;               // invalid row: never kept, never read
    float4 rb = g_boxes[j];
    float  ra = g_area[j];

    unsigned long long bits = 0ull;
#pragma unroll
    for (int b = 0; b < 64; b++) {
        int i = bx * 64 + b;
        if (i > j) {
            float iw = fminf(rb.z, cbox[b].z) - fmaxf(rb.x, cbox[b].x);
            float ih = fminf(rb.w, cbox[b].w) - fmaxf(rb.y, cbox[b].y);
            iw = fmaxf(iw, 0.0f);
            ih = fmaxf(ih, 0.0f);
            float inter = iw * ih;
            float uni = ra + carea[b] - inter;
            if (inter > NMS_T * fmaxf(uni, 1e-9f)) bits |= (1ull << b);
        }
    }
    g_mask[(size_t)j * NW + bx] = bits;
}

// ---------------- kernel 4: exact greedy NMS scan ---------------------------
__global__ void __launch_bounds__(128) scan_kernel() {
    __shared__ unsigned long long remv[NW];
    __shared__ unsigned long long diag[64];
    __shared__ unsigned long long skept;
    int t = threadIdx.x;
    remv[t] = 0ull;
    int V = g_V;
    __syncthreads();

    for (int c = 0; c < NW; c++) {
        if (c * 64 >= V) break;                // rest has no valid entries (keepw stays 0)
        if (t < 64) diag[t] = g_mask[(size_t)(c * 64 + t) * NW + c];
        __syncthreads();

        if (t == 0) {
            int r = V - c * 64;
            unsigned long long vm = (r >= 64) ? ~0ull : ((1ull << r) - 1ull);
            unsigned long long alive = (~remv[c]) & vm;
            unsigned long long kept = 0ull;
            while (alive) {
                int b = __ffsll((long long)alive) - 1;
                kept |= (1ull << b);
                alive &= ~(diag[b] | (1ull << b));
            }
            g_keepw[c] = kept;
            skept = kept;
        }
        __syncthreads();

        if (t > c) {
            unsigned long long km = skept;
            unsigned long long r = remv[t];
            while (km) {
                int b = __ffsll((long long)km) - 1;
                km &= km - 1;
                r |= g_mask[(size_t)(c * 64 + b) * NW + t];
            }
            remv[t] = r;
        }
        __syncthreads();
    }
}

// ---------------- kernel 5: masked output -----------------------------------
__global__ void out_kernel(float* __restrict__ out) {
    int j = blockIdx.x * blockDim.x + threadIdx.x;
    if (j >= M) return;
    unsigned long long kw = g_keepw[j >> 6];
    float f = ((kw >> (j & 63)) & 1ull) ? 1.0f : 0.0f;
#pragma unroll
    for (int c = 0; c < 5; c++)
        out[j * 5 + c] = g_ds[j * 5 + c] * f;
}

// ---------------- launcher ---------------------------------------------------
extern "C" void kernel_launch(void* const* d_in, const int* in_sizes, int n_in,
                              void* d_out, int out_size) {
    const float* det = (const float*)d_in[0];
    const float* off = (const float*)d_in[1];
    const float* scl = (const float*)d_in[2];
    const float* bnd = (const float*)d_in[3];
    float* out = (float*)d_out;

    prep_kernel<<<M / 256, 256>>>(det, off, scl, bnd);
    sort_kernel<<<1, 1024, M * sizeof(unsigned int) + M * sizeof(unsigned short)>>>();
    mask_kernel<<<dim3(NW, NW), 64>>>();
    scan_kernel<<<1, 128>>>();
    out_kernel<<<M / 256, 256>>>(out);
}

// round 3
// speedup vs baseline: 1.2029x; 1.2029x over previous
#include <cuda_runtime.h>
#include <cstdint>

#define M 8192
#define NW 128          // 64-bit words per row (M/64)
#define NMS_T 0.3f

// ---------------- device scratch (no runtime allocation allowed) ------------
__device__ float              g_d[M * 5];       // transformed detections (orig order)
__device__ float              g_score[M];       // score (orig order)
__device__ unsigned int       g_key[M];         // sort key (orig order)
__device__ float              g_ds[M * 5];      // sorted detections
__device__ float              g_ss[M];          // sorted scores
__device__ float4             g_boxes[M];       // x1,y1,x2,y2 (sorted order)
__device__ float              g_area[M];
__device__ int                g_V;              // number of valid (score>0) entries
__device__ unsigned long long g_mask[M * NW];   // suppression bitmask (8 MB)
__device__ unsigned long long g_keepw[NW];      // keep bits

// ---------------- kernel 1: transform + score + sort key --------------------
__global__ void prep_kernel(const float* __restrict__ det,
                            const float* __restrict__ off,
                            const float* __restrict__ scl,
                            const float* __restrict__ bnd) {
    int i = blockIdx.x * blockDim.x + threadIdx.x;
    if (i >= M) return;
    int w = i >> 10;
    const float* dp = det + i * 5;
    float d0 = off[w * 5 + 0] + dp[0] * scl[w * 5 + 0];
    float d1 = off[w * 5 + 1] + dp[1] * scl[w * 5 + 1];
    float d2 = off[w * 5 + 2] + dp[2] * scl[w * 5 + 2];
    float d3 = off[w * 5 + 3] + dp[3] * scl[w * 5 + 3];
    float d4 = off[w * 5 + 4] + dp[4] * scl[w * 5 + 4];
    float cx = dp[1], cy = dp[2];
    bool valid = (cx < bnd[w * 4 + 1]) && (cx > bnd[w * 4 + 0]) &&
                 (cy < bnd[w * 4 + 3]) && (cy > bnd[w * 4 + 2]);
    float score = valid ? d0 : -1.0f;

    g_d[i * 5 + 0] = d0;
    g_d[i * 5 + 1] = d1;
    g_d[i * 5 + 2] = d2;
    g_d[i * 5 + 3] = d3;
    g_d[i * 5 + 4] = d4;
    g_score[i] = score;

    // order-preserving float->uint (ascending), then invert for descending
    unsigned u = __float_as_uint(score);
    u = (u & 0x80000000u) ? ~u : (u | 0x80000000u);
    g_key[i] = ~u;   // ascending key == descending score
}

// ---------------- kernel 2: single-block bitonic sort + gather --------------
// shared: 8192 u32 keys (32KB) + 8192 u16 indices (16KB) = 48KB dynamic
extern "C" __global__ void __launch_bounds__(1024)
sort_kernel() {
    extern __shared__ char smem[];
    unsigned int*   sk = (unsigned int*)smem;
    unsigned short* si = (unsigned short*)(smem + M * sizeof(unsigned int));
    int tid = threadIdx.x;

    for (int t = tid; t < M; t += 1024) {
        sk[t] = g_key[t];
        si[t] = (unsigned short)t;
    }
    __syncthreads();

    for (int k = 2; k <= M; k <<= 1) {
        for (int s = k >> 1; s > 0; s >>= 1) {
            for (int t = tid; t < M; t += 1024) {
                int p = t ^ s;
                if (p > t) {
                    bool up = ((t & k) == 0);
                    unsigned int a = sk[t], b = sk[p];
                    unsigned short ia = si[t], ib = si[p];
                    bool gt = (a > b) || (a == b && ia > ib);
                    if (gt == up) {
                        sk[t] = b; sk[p] = a;
                        si[t] = ib; si[p] = ia;
                    }
                }
            }
            __syncthreads();
        }
    }

    // gather sorted rows, build boxes/areas, find valid count V
    for (int j = tid; j < M; j += 1024) {
        int idx = si[j];
        float dd[5];
#pragma unroll
        for (int c = 0; c < 5; c++) {
            dd[c] = g_d[idx * 5 + c];
            g_ds[j * 5 + c] = dd[c];
        }
        float s = g_score[idx];
        g_ss[j] = s;
        float x1 = dd[1] - 0.5f * dd[3];
        float y1 = dd[2] - 0.5f * dd[4];
        float x2 = dd[1] + 0.5f * dd[3];
        float y2 = dd[2] + 0.5f * dd[4];
        g_boxes[j] = make_float4(x1, y1, x2, y2);
        g_area[j] = fmaxf(x2 - x1, 0.0f) * fmaxf(y2 - y1, 0.0f);

        if (s > 0.0f) {
            if (j == M - 1) g_V = M;
            else if (g_score[si[j + 1]] <= 0.0f) g_V = j + 1;
        } else if (j == 0) {
            g_V = 0;
        }
    }
}

// ---------------- kernel 3: IoU suppression bitmask -------------------------
// block (bx = col chunk, by = row chunk), 64 threads, each = one row
__global__ void mask_kernel() {
    int bx = blockIdx.x, by = blockIdx.y;
    if (bx < by) return;                       // only i > j bits needed
    if (g_ss[by * 64] <= 0.0f) return;         // whole row chunk invalid
    if (g_ss[bx * 64] <= 0.0f) return;         // whole col chunk invalid

    __shared__ float4 cbox[64];
    __shared__ float  carea[64];
    int t = threadIdx.x;
    int ci = bx * 64 + t;
    cbox[t] = g_boxes[ci];
    carea[t] = g_area[ci];
    __syncthreads();

    int j = by * 64 + t;
    if (g_ss[j] <= 0.0f) return;               // invalid row: never kept, never read
    float4 rb = g_boxes[j];
    float  ra = g_area[j];

    unsigned long long bits = 0ull;
#pragma unroll
    for (int b = 0; b < 64; b++) {
        int i = bx * 64 + b;
        if (i > j) {
            float iw = fminf(rb.z, cbox[b].z) - fmaxf(rb.x, cbox[b].x);
            float ih = fminf(rb.w, cbox[b].w) - fmaxf(rb.y, cbox[b].y);
            iw = fmaxf(iw, 0.0f);
            ih = fmaxf(ih, 0.0f);
            float inter = iw * ih;
            float uni = ra + carea[b] - inter;
            if (inter > NMS_T * fmaxf(uni, 1e-9f)) bits |= (1ull << b);
        }
    }
    g_mask[(size_t)j * NW + bx] = bits;
}

// ---------------- kernel 4: exact greedy NMS scan (MLP-4 + diag prefetch) ---
__global__ void __launch_bounds__(128) scan_kernel() {
    __shared__ unsigned long long remv[NW];
    __shared__ unsigned long long sdiag[64];
    __shared__ unsigned long long skept;
    int t = threadIdx.x;
    remv[t] = 0ull;
    int V = g_V;
    int NC = (V + 63) >> 6;       // number of chunks containing valid entries
    int vw = NC - 1;              // last word index worth propagating into

    // prefetch diagonal block of chunk 0
    unsigned long long d = 0ull;
    if (t < 64 && NC > 0) d = g_mask[(size_t)t * NW + 0];
    __syncthreads();

    for (int c = 0; c < NC; c++) {
        if (t < 64) sdiag[t] = d;
        __syncthreads();

        // issue next chunk's diagonal load early (latency hidden by serial+prop)
        if (t < 64 && c + 1 < NC)
            d = g_mask[(size_t)((c + 1) * 64 + t) * NW + (c + 1)];

        if (t == 0) {
            int r = V - c * 64;
            unsigned long long vm = (r >= 64) ? ~0ull : ((1ull << r) - 1ull);
            unsigned long long alive = (~remv[c]) & vm;
            unsigned long long kept = 0ull;
            while (alive) {
                int b = __ffsll((long long)alive) - 1;
                kept |= (1ull << b);
                alive &= ~(sdiag[b] | (1ull << b));
            }
            g_keepw[c] = kept;
            skept = kept;
        }
        __syncthreads();

        // propagate suppression from this chunk's kept rows to later words,
        // with 4 independent loads in flight (MLP=4)
        if (t > c && t <= vw) {
            unsigned long long km = skept;
            const unsigned long long* bp = g_mask + (size_t)(c * 64) * NW + t;
            unsigned long long a0 = 0ull, a1 = 0ull, a2 = 0ull, a3 = 0ull;
            while (km) {
                int b0, b1 = -1, b2 = -1, b3 = -1;
                b0 = __ffsll((long long)km) - 1; km &= km - 1;
                if (km) { b1 = __ffsll((long long)km) - 1; km &= km - 1; }
                if (km) { b2 = __ffsll((long long)km) - 1; km &= km - 1; }
                if (km) { b3 = __ffsll((long long)km) - 1; km &= km - 1; }
                a0 |= bp[(size_t)b0 * NW];
                if (b1 >= 0) a1 |= bp[(size_t)b1 * NW];
                if (b2 >= 0) a2 |= bp[(size_t)b2 * NW];
                if (b3 >= 0) a3 |= bp[(size_t)b3 * NW];
            }
            remv[t] |= (a0 | a1) | (a2 | a3);
        }
        __syncthreads();
    }
}

// ---------------- kernel 5: masked output -----------------------------------
__global__ void out_kernel(float* __restrict__ out) {
    int j = blockIdx.x * blockDim.x + threadIdx.x;
    if (j >= M) return;
    unsigned long long kw = g_keepw[j >> 6];
    float f = ((kw >> (j & 63)) & 1ull) ? 1.0f : 0.0f;
#pragma unroll
    for (int c = 0; c < 5; c++)
        out[j * 5 + c] = g_ds[j * 5 + c] * f;
}

// ---------------- launcher ---------------------------------------------------
extern "C" void kernel_launch(void* const* d_in, const int* in_sizes, int n_in,
                              void* d_out, int out_size) {
    const float* det = (const float*)d_in[0];
    const float* off = (const float*)d_in[1];
    const float* scl = (const float*)d_in[2];
    const float* bnd = (const float*)d_in[3];
    float* out = (float*)d_out;

    prep_kernel<<<M / 256, 256>>>(det, off, scl, bnd);
    sort_kernel<<<1, 1024, M * sizeof(unsigned int) + M * sizeof(unsigned short)>>>();
    mask_kernel<<<dim3(NW, NW), 64>>>();
    scan_kernel<<<1, 128>>>();
    out_kernel<<<M / 256, 256>>>(out);
}

// round 4
// speedup vs baseline: 1.7668x; 1.4688x over previous
#include <cuda_runtime.h>
#include <cstdint>

#define M 8192
#define NW 128          // 64-bit words per row (M/64)
#define NMS_T 0.3f

typedef unsigned long long u64;

// ---------------- device scratch (no runtime allocation allowed) ------------
__device__ float g_d[M * 5];        // transformed detections (orig order)
__device__ u64   g_ckey[M];         // packed (key<<13 | idx) for valid entries
__device__ int   g_cnt;             // valid count (atomic)
__device__ int   g_V;               // valid count (published by sort)
__device__ float g_ds[M * 5];       // sorted detections (first V rows)
__device__ float4 g_boxes[M];       // x1,y1,x2,y2 (sorted order, first V)
__device__ float g_area[M];
__device__ u64   g_mask[M * NW];    // suppression bitmask
__device__ u64   g_keepw[NW];       // keep bits

// ---------------- kernel 0: reset counter -----------------------------------
__global__ void init_kernel() { g_cnt = 0; }

// ---------------- kernel 1: transform + score + compact valid ---------------
__global__ void prep_kernel(const float* __restrict__ det,
                            const float* __restrict__ off,
                            const float* __restrict__ scl,
                            const float* __restrict__ bnd) {
    int i = blockIdx.x * blockDim.x + threadIdx.x;
    if (i >= M) return;
    int w = i >> 10;
    const float* dp = det + i * 5;
    float d0 = off[w * 5 + 0] + dp[0] * scl[w * 5 + 0];
    float d1 = off[w * 5 + 1] + dp[1] * scl[w * 5 + 1];
    float d2 = off[w * 5 + 2] + dp[2] * scl[w * 5 + 2];
    float d3 = off[w * 5 + 3] + dp[3] * scl[w * 5 + 3];
    float d4 = off[w * 5 + 4] + dp[4] * scl[w * 5 + 4];
    float cx = dp[1], cy = dp[2];
    bool valid = (cx < bnd[w * 4 + 1]) && (cx > bnd[w * 4 + 0]) &&
                 (cy < bnd[w * 4 + 3]) && (cy > bnd[w * 4 + 2]);

    g_d[i * 5 + 0] = d0;
    g_d[i * 5 + 1] = d1;
    g_d[i * 5 + 2] = d2;
    g_d[i * 5 + 3] = d3;
    g_d[i * 5 + 4] = d4;

    // only entries with score>0 can be kept; all others produce zero rows and
    // do not influence the positions of positive-score entries (they sort after)
    if (valid && d0 > 0.0f) {
        // positive float: larger float -> larger uint; invert for descending.
        unsigned key = ~(__float_as_uint(d0) | 0x80000000u);
        int pos = atomicAdd(&g_cnt, 1);
        g_ckey[pos] = ((u64)key << 13) | (u64)i;   // (score desc, idx asc)
    }
}

// ---------------- kernel 2: bitonic sort of V packed u64 + gather -----------
extern "C" __global__ void __launch_bounds__(1024)
sort_kernel() {
    extern __shared__ u64 sv[];       // 8192 * 8B = 64KB dynamic
    int tid = threadIdx.x;
    int V = g_cnt;
    if (tid == 0) g_V = V;

    int P = 1;
    while (P < V) P <<= 1;
    if (P < 2) P = 2;

    for (int t = tid; t < P; t += 1024)
        sv[t] = (t < V) ? g_ckey[t] : ~0ull;
    __syncthreads();

    for (int k = 2; k <= P; k <<= 1) {
        for (int s = k >> 1; s > 0; s >>= 1) {
            for (int t = tid; t < P; t += 1024) {
                int p = t ^ s;
                if (p > t) {
                    u64 a = sv[t], b = sv[p];
                    bool up = ((t & k) == 0);
                    if ((a > b) == up) { sv[t] = b; sv[p] = a; }
                }
            }
            __syncthreads();
        }
    }

    // gather sorted rows, build boxes/areas
    for (int j = tid; j < V; j += 1024) {
        int idx = (int)(sv[j] & 0x1FFFu);
        float dd[5];
#pragma unroll
        for (int c = 0; c < 5; c++) {
            dd[c] = g_d[idx * 5 + c];
            g_ds[j * 5 + c] = dd[c];
        }
        float x1 = dd[1] - 0.5f * dd[3];
        float y1 = dd[2] - 0.5f * dd[4];
        float x2 = dd[1] + 0.5f * dd[3];
        float y2 = dd[2] + 0.5f * dd[4];
        g_boxes[j] = make_float4(x1, y1, x2, y2);
        g_area[j] = fmaxf(x2 - x1, 0.0f) * fmaxf(y2 - y1, 0.0f);
    }
}

// ---------------- kernel 3: IoU suppression bitmask -------------------------
__global__ void mask_kernel() {
    int bx = blockIdx.x, by = blockIdx.y;
    if (bx < by) return;                       // only i > j bits needed
    int V = g_V;
    if ((by << 6) >= V || (bx << 6) >= V) return;

    __shared__ float4 cbox[64];
    __shared__ float  carea[64];
    int t = threadIdx.x;
    int ci = (bx << 6) + t;
    if (ci < V) {
        cbox[t] = g_boxes[ci];
        carea[t] = g_area[ci];
    } else {
        cbox[t] = make_float4(0.f, 0.f, 0.f, 0.f);
        carea[t] = 0.f;
    }
    __syncthreads();

    int j = (by << 6) + t;
    if (j >= V) return;
    float4 rb = g_boxes[j];
    float  ra = g_area[j];

    u64 bits = 0ull;
#pragma unroll
    for (int b = 0; b < 64; b++) {
        int i = (bx << 6) + b;
        if (i > j) {
            float iw = fminf(rb.z, cbox[b].z) - fmaxf(rb.x, cbox[b].x);
            float ih = fminf(rb.w, cbox[b].w) - fmaxf(rb.y, cbox[b].y);
            iw = fmaxf(iw, 0.0f);
            ih = fmaxf(ih, 0.0f);
            float inter = iw * ih;
            float uni = ra + carea[b] - inter;
            if (inter > NMS_T * fmaxf(uni, 1e-9f)) bits |= (1ull << b);
        }
    }
    g_mask[(size_t)j * NW + bx] = bits;
}

// ---------------- kernel 4: exact greedy NMS scan ---------------------------
// 512 threads: 4 threads per mask word (MLP 8/word), smem partial fold.
__global__ void __launch_bounds__(512) scan_kernel() {
    __shared__ u64 remv[NW];
    __shared__ u64 sdiag[64];
    __shared__ u64 part[512];
    __shared__ unsigned char klist[64];
    __shared__ int knum;
    int t = threadIdx.x;
    int V = g_V;
    int NC = (V + 63) >> 6;

    if (t < NW) remv[t] = 0ull;

    // prefetch diagonal block of chunk 0
    u64 d = 0ull;
    if (t < 64 && NC > 0) d = g_mask[(size_t)t * NW];
    __syncthreads();

    for (int c = 0; c < NC; c++) {
        if (t < 64) sdiag[t] = d;
        if (c > 0 && t < NW) {
            // fold previous chunk's propagation partials
            remv[t] |= (part[t * 4] | part[t * 4 + 1]) |
                       (part[t * 4 + 2] | part[t * 4 + 3]);
        }
        __syncthreads();

        // issue next chunk's diagonal load early
        if (t < 64 && c + 1 < NC)
            d = g_mask[(size_t)(((c + 1) << 6) + t) * NW + (c + 1)];

        if (t == 0) {
            int r = V - (c << 6);
            u64 vm = (r >= 64) ? ~0ull : ((1ull << r) - 1ull);
            u64 alive = (~remv[c]) & vm;
            u64 kept = 0ull;
            int n = 0;
            while (alive) {
                int b = __ffsll((long long)alive) - 1;
                kept |= (1ull << b);
                klist[n++] = (unsigned char)b;
                alive &= ~(sdiag[b] | (1ull << b));
            }
            g_keepw[c] = kept;
            knum = n;
        }
        __syncthreads();

        // propagate kept rows of chunk c into later words (4 threads/word)
        int w = t >> 2, sub = t & 3;
        u64 a0 = 0ull, a1 = 0ull;
        if (w > c && w < NC) {
            const u64* bp = g_mask + (size_t)(c << 6) * NW + w;
            int n = knum;
            int i = sub;
            for (; i + 4 < n; i += 8) {
                a0 |= bp[(size_t)klist[i] * NW];
                a1 |= bp[(size_t)klist[i + 4] * NW];
            }
            if (i < n) a0 |= bp[(size_t)klist[i] * NW];
        }
        part[t] = a0 | a1;
        __syncthreads();
    }
}

// ---------------- kernel 5: masked output -----------------------------------
__global__ void out_kernel(float* __restrict__ out) {
    int j = blockIdx.x * blockDim.x + threadIdx.x;
    if (j >= M) return;
    int V = g_V;
    if (j < V) {
        u64 kw = g_keepw[j >> 6];
        float f = ((kw >> (j & 63)) & 1ull) ? 1.0f : 0.0f;
#pragma unroll
        for (int c = 0; c < 5; c++)
            out[j * 5 + c] = g_ds[j * 5 + c] * f;
    } else {
#pragma unroll
        for (int c = 0; c < 5; c++)
            out[j * 5 + c] = 0.0f;
    }
}

// ---------------- launcher ---------------------------------------------------
extern "C" void kernel_launch(void* const* d_in, const int* in_sizes, int n_in,
                              void* d_out, int out_size) {
    const float* det = (const float*)d_in[0];
    const float* off = (const float*)d_in[1];
    const float* scl = (const float*)d_in[2];
    const float* bnd = (const float*)d_in[3];
    float* out = (float*)d_out;

    cudaFuncSetAttribute((const void*)sort_kernel,
                         cudaFuncAttributeMaxDynamicSharedMemorySize, 65536);

    init_kernel<<<1, 1>>>();
    prep_kernel<<<M / 256, 256>>>(det, off, scl, bnd);
    sort_kernel<<<1, 1024, 65536>>>();
    mask_kernel<<<dim3(NW, NW), 64>>>();
    scan_kernel<<<1, 512>>>();
    out_kernel<<<M / 256, 256>>>(out);
}

// round 5
// speedup vs baseline: 2.1536x; 1.2189x over previous
#include <cuda_runtime.h>
#include <cstdint>

#define M 8192
#define NW 128          // 64-bit words per row (M/64)
#define NMS_T 0.3f
#define CH 256          // scan chunk size (elements)
#define WPC 4           // words per chunk (CH/64)

typedef unsigned long long u64;

// ---------------- device scratch (no runtime allocation allowed) ------------
__device__ float g_d[M * 5];        // transformed detections (orig order)
__device__ u64   g_ckey[M];         // packed (key<<13 | idx) for valid entries
__device__ int   g_cnt;             // valid count (atomic; reset by out_kernel)
__device__ int   g_V;               // valid count (published by sort)
__device__ float g_ds[M * 5];       // sorted detections (first V rows)
__device__ float4 g_boxes[M];       // x1,y1,x2,y2 (sorted order, first V)
__device__ float g_area[M];
__device__ u64   g_mask[M * NW];    // suppression bitmask (i>j bits only)
__device__ u64   g_keepw[NW];       // keep bits

// ---------------- kernel 1: transform + score + compact valid ---------------
__global__ void prep_kernel(const float* __restrict__ det,
                            const float* __restrict__ off,
                            const float* __restrict__ scl,
                            const float* __restrict__ bnd) {
    int i = blockIdx.x * blockDim.x + threadIdx.x;
    if (i >= M) return;
    int w = i >> 10;
    const float* dp = det + i * 5;
    float d0 = off[w * 5 + 0] + dp[0] * scl[w * 5 + 0];
    float d1 = off[w * 5 + 1] + dp[1] * scl[w * 5 + 1];
    float d2 = off[w * 5 + 2] + dp[2] * scl[w * 5 + 2];
    float d3 = off[w * 5 + 3] + dp[3] * scl[w * 5 + 3];
    float d4 = off[w * 5 + 4] + dp[4] * scl[w * 5 + 4];
    float cx = dp[1], cy = dp[2];
    bool valid = (cx < bnd[w * 4 + 1]) && (cx > bnd[w * 4 + 0]) &&
                 (cy < bnd[w * 4 + 3]) && (cy > bnd[w * 4 + 2]);

    g_d[i * 5 + 0] = d0;
    g_d[i * 5 + 1] = d1;
    g_d[i * 5 + 2] = d2;
    g_d[i * 5 + 3] = d3;
    g_d[i * 5 + 4] = d4;

    // only entries with score>0 can be kept; all others produce zero rows and
    // sort after every positive-score entry, so their order is irrelevant
    if (valid && d0 > 0.0f) {
        unsigned key = ~(__float_as_uint(d0) | 0x80000000u);
        int pos = atomicAdd(&g_cnt, 1);
        g_ckey[pos] = ((u64)key << 13) | (u64)i;   // (score desc, idx asc)
    }
}

// ---------------- kernel 2: bitonic sort of V packed u64 + gather -----------
extern "C" __global__ void __launch_bounds__(1024)
sort_kernel() {
    extern __shared__ u64 sv[];       // up to 8192 * 8B = 64KB dynamic
    int tid = threadIdx.x;
    int V = g_cnt;
    if (tid == 0) g_V = V;

    int P = 1;
    while (P < V) P <<= 1;
    if (P < 2) P = 2;

    for (int t = tid; t < P; t += 1024)
        sv[t] = (t < V) ? g_ckey[t] : ~0ull;
    __syncthreads();

    for (int k = 2; k <= P; k <<= 1) {
        for (int s = k >> 1; s > 0; s >>= 1) {
            for (int t = tid; t < P; t += 1024) {
                int p = t ^ s;
                if (p > t) {
                    u64 a = sv[t], b = sv[p];
                    bool up = ((t & k) == 0);
                    if ((a > b) == up) { sv[t] = b; sv[p] = a; }
                }
            }
            __syncthreads();
        }
    }

    // gather sorted rows, build boxes/areas
    for (int j = tid; j < V; j += 1024) {
        int idx = (int)(sv[j] & 0x1FFFu);
        float dd[5];
#pragma unroll
        for (int c = 0; c < 5; c++) {
            dd[c] = g_d[idx * 5 + c];
            g_ds[j * 5 + c] = dd[c];
        }
        float x1 = dd[1] - 0.5f * dd[3];
        float y1 = dd[2] - 0.5f * dd[4];
        float x2 = dd[1] + 0.5f * dd[3];
        float y2 = dd[2] + 0.5f * dd[4];
        g_boxes[j] = make_float4(x1, y1, x2, y2);
        g_area[j] = fmaxf(x2 - x1, 0.0f) * fmaxf(y2 - y1, 0.0f);
    }
}

// ---------------- kernel 3: IoU suppression bitmask -------------------------
__global__ void mask_kernel() {
    int bx = blockIdx.x, by = blockIdx.y;
    if (bx < by) return;                       // only i > j bits needed
    int V = g_V;
    if ((by << 6) >= V || (bx << 6) >= V) return;

    __shared__ float4 cbox[64];
    __shared__ float  carea[64];
    int t = threadIdx.x;
    int ci = (bx << 6) + t;
    if (ci < V) {
        cbox[t] = g_boxes[ci];
        carea[t] = g_area[ci];
    } else {
        cbox[t] = make_float4(0.f, 0.f, 0.f, 0.f);
        carea[t] = 0.f;
    }
    __syncthreads();

    int j = (by << 6) + t;
    if (j >= V) return;
    float4 rb = g_boxes[j];
    float  ra = g_area[j];

    u64 bits = 0ull;
#pragma unroll
    for (int b = 0; b < 64; b++) {
        int i = (bx << 6) + b;
        if (i > j) {
            float iw = fminf(rb.z, cbox[b].z) - fmaxf(rb.x, cbox[b].x);
            float ih = fminf(rb.w, cbox[b].w) - fmaxf(rb.y, cbox[b].y);
            iw = fmaxf(iw, 0.0f);
            ih = fmaxf(ih, 0.0f);
            float inter = iw * ih;
            float uni = ra + carea[b] - inter;
            if (inter > NMS_T * fmaxf(uni, 1e-9f)) bits |= (1ull << b);
        }
    }
    g_mask[(size_t)j * NW + bx] = bits;
}

// ---------------- kernel 4: exact greedy NMS scan, 256-wide chunks ----------
__global__ void __launch_bounds__(512) scan_kernel() {
    __shared__ u64 remv[NW];
    __shared__ u64 sdiag[CH][WPC];        // 8KB diagonal block
    __shared__ u64 part[512];             // propagation partials
    __shared__ unsigned short klist[CH];
    __shared__ int knum;
    int t = threadIdx.x;
    int V = g_V;
    int NC = (V + CH - 1) / CH;           // 256-wide chunks
    int NWv = (V + 63) >> 6;              // words containing valid entries

    if (t < NW) remv[t] = 0ull;
    part[t] = 0ull;

    // prefetch diag block of chunk 0: idx -> (row=idx>>2, word=idx&3)
    u64 d0 = 0ull, d1 = 0ull;
    if (NC > 0) {
        int i0 = t, i1 = t + 512;
        d0 = g_mask[(size_t)(i0 >> 2) * NW + (i0 & 3)];
        d1 = g_mask[(size_t)(i1 >> 2) * NW + (i1 & 3)];
    }
    __syncthreads();

    for (int c = 0; c < NC; c++) {
        // store prefetched diag block
        sdiag[t >> 2][t & 3] = d0;
        sdiag[(t + 512) >> 2][(t + 512) & 3] = d1;
        // fold prev chunk's propagation partials: word c*4 + u  (u = t < 128)
        if (t < NW) {
            int w = c * WPC + t;
            if (w < NW)
                remv[w] |= (part[t * 4] | part[t * 4 + 1]) |
                           (part[t * 4 + 2] | part[t * 4 + 3]);
        }
        __syncthreads();

        // prefetch next chunk's diag block (latency hidden by greedy+prop)
        if (c + 1 < NC) {
            int base = (c + 1) * CH;
            int i0 = t, i1 = t + 512;
            d0 = g_mask[(size_t)(base + (i0 >> 2)) * NW + ((c + 1) * WPC + (i0 & 3))];
            d1 = g_mask[(size_t)(base + (i1 >> 2)) * NW + ((c + 1) * WPC + (i1 & 3))];
        }

        if (t == 0) {
            u64 alive[WPC], kept[WPC];
#pragma unroll
            for (int w = 0; w < WPC; w++) {
                int gw = c * WPC + w;
                int r = V - (gw << 6);
                u64 vm = (r >= 64) ? ~0ull : (r <= 0 ? 0ull : ((1ull << r) - 1ull));
                alive[w] = ~remv[gw] & vm;
                kept[w] = 0ull;
            }
            int n = 0;
            for (int w = 0; w < WPC; w++) {
                while (alive[w]) {
                    int b = __ffsll((long long)alive[w]) - 1;
                    int r = (w << 6) + b;
                    kept[w] |= 1ull << b;
                    klist[n++] = (unsigned short)r;
                    alive[w] &= ~(1ull << b);
#pragma unroll
                    for (int u = 0; u < WPC; u++)
                        alive[u] &= ~sdiag[r][u];   // bits only for i > global r
                }
            }
#pragma unroll
            for (int w = 0; w < WPC; w++) g_keepw[c * WPC + w] = kept[w];
            knum = n;
        }
        __syncthreads();

        // propagation: 4 threads per word, 4 accumulators each (MLP 16/word)
        int w = c * WPC + WPC + (t >> 2);
        int sub = t & 3;
        u64 a0 = 0ull, a1 = 0ull, a2 = 0ull, a3 = 0ull;
        if (w < NWv) {
            const u64* bp = g_mask + (size_t)(c * CH) * NW + w;
            int n = knum;
            int i = sub;
            for (; i + 12 < n; i += 16) {
                a0 |= bp[(size_t)klist[i] * NW];
                a1 |= bp[(size_t)klist[i + 4] * NW];
                a2 |= bp[(size_t)klist[i + 8] * NW];
                a3 |= bp[(size_t)klist[i + 12] * NW];
            }
            for (; i < n; i += 4) a0 |= bp[(size_t)klist[i] * NW];
        }
        part[t] = (a0 | a1) | (a2 | a3);
        __syncthreads();
    }
}

// ---------------- kernel 5: masked output + counter reset -------------------
__global__ void out_kernel(float* __restrict__ out) {
    int j = blockIdx.x * blockDim.x + threadIdx.x;
    if (j == 0) g_cnt = 0;          // deterministic reset for next invocation
    if (j >= M) return;
    int V = g_V;
    if (j < V) {
        u64 kw = g_keepw[j >> 6];
        float f = ((kw >> (j & 63)) & 1ull) ? 1.0f : 0.0f;
#pragma unroll
        for (int c = 0; c < 5; c++)
            out[j * 5 + c] = g_ds[j * 5 + c] * f;
    } else {
#pragma unroll
        for (int c = 0; c < 5; c++)
            out[j * 5 + c] = 0.0f;
    }
}

// ---------------- launcher ---------------------------------------------------
extern "C" void kernel_launch(void* const* d_in, const int* in_sizes, int n_in,
                              void* d_out, int out_size) {
    const float* det = (const float*)d_in[0];
    const float* off = (const float*)d_in[1];
    const float* scl = (const float*)d_in[2];
    const float* bnd = (const float*)d_in[3];
    float* out = (float*)d_out;

    cudaFuncSetAttribute((const void*)sort_kernel,
                         cudaFuncAttributeMaxDynamicSharedMemorySize, 65536);

    prep_kernel<<<M / 256, 256>>>(det, off, scl, bnd);
    sort_kernel<<<1, 1024, 65536>>>();
    mask_kernel<<<dim3(NW, NW), 64>>>();
    scan_kernel<<<1, 512>>>();
    out_kernel<<<M / 256, 256>>>(out);
}